// round 13
// baseline (speedup 1.0000x reference)
#include <cuda_runtime.h>
#include <cuda_bf16.h>
#include <math.h>

#define S_LEN 2048
#define HID_D 2048
#define NH 16
#define HD 128
#define DR 64
#define DQK 192
#define CKV 512
#define CQ 1536

// ---------------- scratch ----------------------------------------------------
__device__ unsigned g_Xt  [S_LEN * HID_D];     // tf32 bits, k-pair-permuted (A operand)
__device__ unsigned g_Wdkv[HID_D * CKV];
__device__ unsigned g_Wuk [CKV * NH * HD];
__device__ unsigned g_Wuv [CKV * NH * HD];
__device__ unsigned g_Wdq [HID_D * CQ];
__device__ unsigned g_Wuq [CQ * NH * HD];
__device__ unsigned g_Wqr [CQ * NH * DR];
__device__ unsigned g_Wkr [HID_D * DR];
__device__ unsigned g_Wo  [NH * HD * HID_D];
__device__ unsigned g_cKVt[S_LEN * CKV];       // tf32 bits, A-permuted
__device__ unsigned g_cQt [S_LEN * CQ];
__device__ unsigned g_AO  [S_LEN * NH * HD];   // tf32 bits, A-permuted
__device__ float g_qR [S_LEN * NH * DR];
__device__ float g_kR [S_LEN * DR];
__device__ unsigned short g_QH[NH * S_LEN * DQK];   // bf16 hi, natural order
__device__ unsigned short g_QL[NH * S_LEN * DQK];
__device__ unsigned short g_KH[NH * S_LEN * DQK];
__device__ unsigned short g_KL[NH * S_LEN * DQK];
__device__ unsigned short g_VH2[NH * S_LEN * HD];   // bf16 hi, [h][s][128]
__device__ unsigned short g_VL2[NH * S_LEN * HD];

// tf32 A-operand pair-permutation within an 8-chunk
__device__ __forceinline__ int pa8(int c) {
    return ((c & 3) << 1) | (c >> 2);
}

// ---------------- tf32 / bf16 helpers ---------------------------------------
__device__ __forceinline__ unsigned f2tf(float x) {
    unsigned u;
    asm("cvt.rna.tf32.f32 %0, %1;" : "=r"(u) : "f"(x));
    return u;
}

__device__ __forceinline__ void mma8(float c[4], const unsigned a[4], const unsigned b[2]) {
    asm volatile(
        "mma.sync.aligned.m16n8k8.row.col.f32.tf32.tf32.f32 "
        "{%0,%1,%2,%3}, {%4,%5,%6,%7}, {%8,%9}, {%0,%1,%2,%3};\n"
        : "+f"(c[0]), "+f"(c[1]), "+f"(c[2]), "+f"(c[3])
        : "r"(a[0]), "r"(a[1]), "r"(a[2]), "r"(a[3]), "r"(b[0]), "r"(b[1]));
}

__device__ __forceinline__ void mma16(float c[4], const unsigned a[4],
                                      unsigned b0, unsigned b1) {
    asm volatile(
        "mma.sync.aligned.m16n8k16.row.col.f32.bf16.bf16.f32 "
        "{%0,%1,%2,%3}, {%4,%5,%6,%7}, {%8,%9}, {%0,%1,%2,%3};\n"
        : "+f"(c[0]), "+f"(c[1]), "+f"(c[2]), "+f"(c[3])
        : "r"(a[0]), "r"(a[1]), "r"(a[2]), "r"(a[3]), "r"(b0), "r"(b1));
}

__device__ __forceinline__ void ldsm4(unsigned r[4], unsigned addr) {
    asm volatile("ldmatrix.sync.aligned.m8n8.x4.shared.b16 {%0,%1,%2,%3}, [%4];"
                 : "=r"(r[0]), "=r"(r[1]), "=r"(r[2]), "=r"(r[3]) : "r"(addr));
}
__device__ __forceinline__ void ldsm4t(unsigned r[4], unsigned addr) {
    asm volatile("ldmatrix.sync.aligned.m8n8.x4.trans.shared.b16 {%0,%1,%2,%3}, [%4];"
                 : "=r"(r[0]), "=r"(r[1]), "=r"(r[2]), "=r"(r[3]) : "r"(addr));
}

__device__ __forceinline__ void split2(float x, unsigned short &hh, unsigned short &ll) {
    __nv_bfloat16 bh = __float2bfloat16(x);
    float hf = __bfloat162float(bh);
    __nv_bfloat16 bl = __float2bfloat16(x - hf);
    hh = __bfloat16_as_ushort(bh);
    ll = __bfloat16_as_ushort(bl);
}

__device__ __forceinline__ unsigned bfbits(float x) {
    return (unsigned)__bfloat16_as_ushort(__float2bfloat16(x));
}
__device__ __forceinline__ float bfval(float x) {
    return __bfloat162float(__float2bfloat16(x));
}
__device__ __forceinline__ unsigned packsplit(float x, float y, unsigned &lo) {
    float xh = bfval(x), yh = bfval(y);
    unsigned hi = bfbits(x) | (bfbits(y) << 16);
    lo = bfbits(x - xh) | (bfbits(y - yh) << 16);
    return hi;
}

__device__ __forceinline__ void cp16(void* dst_smem, const void* src, bool pred) {
    unsigned saddr = (unsigned)__cvta_generic_to_shared(dst_smem);
    int sz = pred ? 16 : 0;
    asm volatile("cp.async.cg.shared.global [%0], [%1], 16, %2;\n"
                 :: "r"(saddr), "l"(src), "r"(sz));
}

// ---------------- preconvert: f32 -> tf32 bits (optionally A-permuted) -------
struct CvtArgs {
    const float* src[9];
    unsigned*    dst[9];
    int tstart[10];
    int perm[9];
};

__global__ __launch_bounds__(256)
void cvt_kernel(CvtArgs ca)
{
    int g = 0;
    while ((int)blockIdx.x >= ca.tstart[g + 1]) g++;
    int idx = (blockIdx.x - ca.tstart[g]) * 1024 + threadIdx.x * 4;
    float4 v = *(const float4*)&ca.src[g][idx];
    if (!ca.perm[g]) {
        uint4 u = make_uint4(f2tf(v.x), f2tf(v.y), f2tf(v.z), f2tf(v.w));
        *(uint4*)&ca.dst[g][idx] = u;
    } else {
        int b8 = idx & ~7;
        int c0 = idx & 7;
        unsigned* d = ca.dst[g] + b8;
        d[pa8(c0 + 0)] = f2tf(v.x);
        d[pa8(c0 + 1)] = f2tf(v.y);
        d[pa8(c0 + 2)] = f2tf(v.z);
        d[pa8(c0 + 3)] = f2tf(v.w);
    }
}

// ---------------- grouped tf32 GEMM with cp.async pipeline -------------------
// modes: 0 = f32 row-major (guarded), 1 = bf16 hi/lo head-split 192 (Q/K),
//        3 = tf32-bits A-permuted, 4 = bf16 hi/lo head-split 128 (V)
#define GSTAGES 3
#define GEMM_SMEM (GSTAGES * (2560 + 2176) * 4)

struct GroupArgs {
    const unsigned* A[4];
    const unsigned* B[4];
    void*        C[4];
    void*        Clo[4];
    int K[4];
    int N[4];
    int mode[4];
    int tstart[5];
};

__global__ __launch_bounds__(256, 2)
void mma_gemm_grouped(GroupArgs ga)
{
    extern __shared__ unsigned gsm[];
    unsigned* As = gsm;
    unsigned* Bs = gsm + GSTAGES * 2560;

    int g = 0;
    while (blockIdx.y >= (unsigned)ga.tstart[g + 1]) g++;
    const unsigned* __restrict__ A = ga.A[g];
    const unsigned* __restrict__ B = ga.B[g];
    const int K = ga.K[g];
    const int N = ga.N[g];
    const int mode = ga.mode[g];

    const int tid  = threadIdx.x;
    const int lane = tid & 31;
    const int warp = tid >> 5;
    const int wm   = warp & 1;
    const int wn   = warp >> 1;
    const int m0   = blockIdx.x * 128;
    const int n0   = (blockIdx.y - ga.tstart[g]) * 128;
    const int fr   = lane >> 2;
    const int fc   = lane & 3;

    float acc[4][4][4];
#pragma unroll
    for (int mt = 0; mt < 4; mt++)
#pragma unroll
        for (int nt = 0; nt < 4; nt++)
#pragma unroll
            for (int i = 0; i < 4; i++) acc[mt][nt][i] = 0.f;

    const int rowA0 = (tid + 0)   >> 2;   const int kcA0 = ((tid + 0)   & 3) * 4;
    const int rowA1 = (tid + 256) >> 2;   const int kcA1 = ((tid + 256) & 3) * 4;
    const int kkB0  = (tid + 0)   >> 5;   const int c4B0 = ((tid + 0)   & 31) * 4;
    const int kkB1  = (tid + 256) >> 5;   const int c4B1 = ((tid + 256) & 31) * 4;
    const bool pb0 = (n0 + c4B0 < N);
    const bool pb1 = (n0 + c4B1 < N);

    const int ktiles = K >> 4;

#define GLOAD(kt, st)                                                           \
    {                                                                           \
        cp16(&As[(st) * 2560 + rowA0 * 20 + kcA0],                              \
             &A[(size_t)(m0 + rowA0) * K + (kt) * 16 + kcA0], true);            \
        cp16(&As[(st) * 2560 + rowA1 * 20 + kcA1],                              \
             &A[(size_t)(m0 + rowA1) * K + (kt) * 16 + kcA1], true);            \
        cp16(&Bs[(st) * 2176 + kkB0 * 136 + c4B0],                              \
             &B[(size_t)((kt) * 16 + kkB0) * N + n0 + c4B0], pb0);              \
        cp16(&Bs[(st) * 2176 + kkB1 * 136 + c4B1],                              \
             &B[(size_t)((kt) * 16 + kkB1) * N + n0 + c4B1], pb1);              \
    }

#pragma unroll
    for (int s = 0; s < GSTAGES - 1; s++) {
        GLOAD(s, s);
        asm volatile("cp.async.commit_group;\n");
    }

#pragma unroll 1
    for (int i = 0; i < ktiles; i++) {
        asm volatile("cp.async.wait_group %0;\n" :: "n"(GSTAGES - 2));
        __syncthreads();
        int nf = i + GSTAGES - 1;
        if (nf < ktiles) GLOAD(nf, nf % GSTAGES);
        asm volatile("cp.async.commit_group;\n");

        const unsigned* Asb = As + (i % GSTAGES) * 2560;
        const unsigned* Bsb = Bs + (i % GSTAGES) * 2176;
#pragma unroll
        for (int ks = 0; ks < 2; ks++) {
            unsigned af[4][4], bf[4][2];
#pragma unroll
            for (int mt = 0; mt < 4; mt++) {
                int mr = wm * 64 + mt * 16 + fr;
                uint2 p0 = *(const uint2*)&Asb[mr * 20 + ks * 8 + 2 * fc];
                uint2 p1 = *(const uint2*)&Asb[(mr + 8) * 20 + ks * 8 + 2 * fc];
                af[mt][0] = p0.x; af[mt][1] = p1.x; af[mt][2] = p0.y; af[mt][3] = p1.y;
            }
#pragma unroll
            for (int nt = 0; nt < 4; nt++) {
                int nc = wn * 32 + nt * 8 + fr;
                bf[nt][0] = Bsb[(ks * 8 + fc) * 136 + nc];
                bf[nt][1] = Bsb[(ks * 8 + fc + 4) * 136 + nc];
            }
#pragma unroll
            for (int mt = 0; mt < 4; mt++)
#pragma unroll
                for (int nt = 0; nt < 4; nt++)
                    mma8(acc[mt][nt], af[mt], bf[nt]);
        }
    }
#undef GLOAD

    // ---- epilogue ----
#pragma unroll
    for (int mt = 0; mt < 4; mt++) {
#pragma unroll
        for (int nt = 0; nt < 4; nt++) {
            int row = m0 + wm * 64 + mt * 16 + fr;
            int col = n0 + wn * 32 + nt * 8 + fc * 2;
            if (mode == 0) {
                float* Cf = (float*)ga.C[g];
                if (col < N) {
                    *(float2*)&Cf[(size_t)row * N + col] =
                        make_float2(acc[mt][nt][0], acc[mt][nt][1]);
                    *(float2*)&Cf[(size_t)(row + 8) * N + col] =
                        make_float2(acc[mt][nt][2], acc[mt][nt][3]);
                }
            } else if (mode == 1) {
                unsigned short* CH = (unsigned short*)ga.C[g];
                unsigned short* CL = (unsigned short*)ga.Clo[g];
                int hh = col >> 7, d = col & 127;
                size_t b0 = ((size_t)(hh * S_LEN + row)) * DQK + d;
                size_t b1 = ((size_t)(hh * S_LEN + row + 8)) * DQK + d;
                unsigned lo, hi;
                hi = packsplit(acc[mt][nt][0], acc[mt][nt][1], lo);
                *(unsigned*)&CH[b0] = hi; *(unsigned*)&CL[b0] = lo;
                hi = packsplit(acc[mt][nt][2], acc[mt][nt][3], lo);
                *(unsigned*)&CH[b1] = hi; *(unsigned*)&CL[b1] = lo;
            } else if (mode == 4) {
                unsigned short* CH = (unsigned short*)ga.C[g];
                unsigned short* CL = (unsigned short*)ga.Clo[g];
                int hh = col >> 7, d = col & 127;
                size_t b0 = ((size_t)(hh * S_LEN + row)) * HD + d;
                size_t b1 = ((size_t)(hh * S_LEN + row + 8)) * HD + d;
                unsigned lo, hi;
                hi = packsplit(acc[mt][nt][0], acc[mt][nt][1], lo);
                *(unsigned*)&CH[b0] = hi; *(unsigned*)&CL[b0] = lo;
                hi = packsplit(acc[mt][nt][2], acc[mt][nt][3], lo);
                *(unsigned*)&CH[b1] = hi; *(unsigned*)&CL[b1] = lo;
            } else {
                unsigned* Cu = (unsigned*)ga.C[g];
                int base = col & ~7;
                int o0 = pa8(col & 7);
                Cu[(size_t)row * N + base + o0]     = f2tf(acc[mt][nt][0]);
                Cu[(size_t)row * N + base + o0 + 2] = f2tf(acc[mt][nt][1]);
                Cu[(size_t)(row + 8) * N + base + o0]     = f2tf(acc[mt][nt][2]);
                Cu[(size_t)(row + 8) * N + base + o0 + 2] = f2tf(acc[mt][nt][3]);
            }
        }
    }
}

// ---------------- prep kernels (natural order) -------------------------------
__global__ void rope_q_kernel()
{
    int idx = blockIdx.x * blockDim.x + threadIdx.x;
    if (idx >= S_LEN * NH * 32) return;
    int i = idx & 31;
    int h = (idx >> 5) & 15;
    int t = idx >> 9;
    float invf = powf(10000.0f, -(2.0f * i) / 64.0f);
    float ang = (float)t * invf;
    float s, c;
    sincosf(ang, &s, &c);
    const float* x = g_qR + (size_t)t * (NH * DR) + h * DR;
    float x1 = x[i], x2 = x[i + 32];
    float r1 = x1 * c - x2 * s;
    float r2 = x2 * c + x1 * s;
    size_t base = ((size_t)(h * S_LEN + t)) * DQK;
    unsigned short hh, ll;
    split2(r1, hh, ll); g_QH[base + 128 + i] = hh; g_QL[base + 128 + i] = ll;
    split2(r2, hh, ll); g_QH[base + 160 + i] = hh; g_QL[base + 160 + i] = ll;
}

__global__ void rope_k_kernel()
{
    int idx = blockIdx.x * blockDim.x + threadIdx.x;
    if (idx >= S_LEN * 32) return;
    int i = idx & 31;
    int t = idx >> 5;
    float invf = powf(10000.0f, -(2.0f * i) / 64.0f);
    float ang = (float)t * invf;
    float s, c;
    sincosf(ang, &s, &c);
    const float* x = g_kR + (size_t)t * DR;
    float r1 = x[i] * c - x[i + 32] * s;
    float r2 = x[i + 32] * c + x[i] * s;
    unsigned short h1, l1, h2, l2;
    split2(r1, h1, l1);
    split2(r2, h2, l2);
#pragma unroll
    for (int h = 0; h < NH; h++) {
        size_t base = ((size_t)(h * S_LEN + t)) * DQK;
        g_KH[base + 128 + i] = h1; g_KL[base + 128 + i] = l1;
        g_KH[base + 160 + i] = h2; g_KL[base + 160 + i] = l2;
    }
}

// ---------------- bf16x3 flash attention: ldmatrix + cp.async ----------------
// smem (ushort strides): QH[128][216]@0, QL@55296, KH[64][216]@110592,
// KL@138240, VH[64][136]@165888, VL@183296    total 200704
#define ATTN_SMEM 200704
#define QKSTR 216

__global__ __launch_bounds__(256, 1)
void attn_mma_kernel()
{
    extern __shared__ char smraw[];
    unsigned short* QH = (unsigned short*)(smraw);
    unsigned short* QL = (unsigned short*)(smraw + 55296);
    unsigned short* KH = (unsigned short*)(smraw + 110592);
    unsigned short* KL = (unsigned short*)(smraw + 138240);
    unsigned short* VH = (unsigned short*)(smraw + 165888);
    unsigned short* VL = (unsigned short*)(smraw + 183296);

    const int bid  = blockIdx.x;
    const int mb   = 15 - (bid >> 4);
    const int h    = bid & 15;
    const int m0   = mb * 128;
    const int tid  = threadIdx.x;
    const int lane = tid & 31;
    const int warp = tid >> 5;
    const int g = lane >> 2, t = lane & 3;

    const uint4* KHg = (const uint4*)(g_KH + (size_t)h * S_LEN * DQK);
    const uint4* KLg = (const uint4*)(g_KL + (size_t)h * S_LEN * DQK);
    const uint4* VHg = (const uint4*)(g_VH2 + (size_t)h * S_LEN * HD);
    const uint4* VLg = (const uint4*)(g_VL2 + (size_t)h * S_LEN * HD);
    uint4* KH4 = (uint4*)KH;
    uint4* KL4 = (uint4*)KL;
    uint4* VH4 = (uint4*)VH;
    uint4* VL4 = (uint4*)VL;

#define CPK(nn)                                                                 \
    {                                                                           \
        const uint4* sH = KHg + (size_t)(nn) * 24;                              \
        const uint4* sL = KLg + (size_t)(nn) * 24;                              \
        _Pragma("unroll")                                                       \
        for (int i = 0; i < 6; i++) {                                           \
            int idx = tid + i * 256;                                            \
            int r = idx / 24, u = idx - r * 24;                                 \
            cp16(&KH4[r * 27 + u], &sH[idx], true);                             \
            cp16(&KL4[r * 27 + u], &sL[idx], true);                             \
        }                                                                       \
    }
#define CPV(nn)                                                                 \
    {                                                                           \
        const uint4* sH = VHg + (size_t)(nn) * 16;                              \
        const uint4* sL = VLg + (size_t)(nn) * 16;                              \
        _Pragma("unroll")                                                       \
        for (int i = 0; i < 4; i++) {                                           \
            int idx = tid + i * 256;                                            \
            int r = idx >> 4, u = idx & 15;                                     \
            cp16(&VH4[r * 17 + u], &sH[idx], true);                             \
            cp16(&VL4[r * 17 + u], &sL[idx], true);                             \
        }                                                                       \
    }

    CPK(0);
    asm volatile("cp.async.commit_group;\n");
    CPV(0);
    asm volatile("cp.async.commit_group;\n");

    // stage Q while tile 0 lands
    {
        const uint4* sH = (const uint4*)(g_QH + ((size_t)h * S_LEN + m0) * DQK);
        const uint4* sL = (const uint4*)(g_QL + ((size_t)h * S_LEN + m0) * DQK);
        uint4* dH = (uint4*)QH;
        uint4* dL = (uint4*)QL;
#pragma unroll
        for (int i = 0; i < 12; i++) {
            int idx = tid + i * 256;
            int r = idx / 24, u = idx - r * 24;
            dH[r * 27 + u] = sH[idx];
            dL[r * 27 + u] = sL[idx];
        }
    }

    // ldmatrix per-thread base addresses
    const unsigned QHs = (unsigned)__cvta_generic_to_shared(QH);
    const unsigned QLs = (unsigned)__cvta_generic_to_shared(QL);
    const unsigned KHs = (unsigned)__cvta_generic_to_shared(KH);
    const unsigned KLs = (unsigned)__cvta_generic_to_shared(KL);
    const unsigned VHs = (unsigned)__cvta_generic_to_shared(VH);
    const unsigned VLs = (unsigned)__cvta_generic_to_shared(VL);
    // Q (non-trans): rows warp*16 + (lane&15), k-off (lane>>4)*8
    const unsigned qoff = ((warp * 16 + (lane & 15)) * QKSTR + (lane >> 4) * 8) * 2;
    // K (non-trans): rows n = (lane&15) within 16-n group, k-off (lane>>4)*8
    const unsigned koff = ((lane & 15) * QKSTR + (lane >> 4) * 8) * 2;
    // V (.trans): rows s = (lane&15) within 16-s chunk, d-off (lane>>4)*8
    const unsigned voff = ((lane & 15) * 136 + (lane >> 4) * 8) * 2;

    float oacc[16][4];
#pragma unroll
    for (int nt = 0; nt < 16; nt++)
#pragma unroll
        for (int c = 0; c < 4; c++) oacc[nt][c] = 0.f;

    float mrow[2] = {-1e30f, -1e30f};
    float lrow[2] = {0.f, 0.f};

    const float scale = 0.07216878364870322f;
    const int ntiles = 2 * mb + 2;

    asm volatile("cp.async.wait_group 0;\n");
    __syncthreads();

#pragma unroll 1
    for (int tile = 0; tile < ntiles; tile++) {
        const int n0 = tile * 64;
        const int npf = (tile + 1 < ntiles) ? (tile + 1) * 64 : 0;

        // ---- S = Q K^T ----
        float sacc[8][4];
#pragma unroll
        for (int nt = 0; nt < 8; nt++)
#pragma unroll
            for (int c = 0; c < 4; c++) sacc[nt][c] = 0.f;

#pragma unroll
        for (int kt = 0; kt < 12; kt++) {
            unsigned ah[4], al[4];
            ldsm4(ah, QHs + qoff + kt * 32);
            ldsm4(al, QLs + qoff + kt * 32);
#pragma unroll
            for (int p = 0; p < 4; p++) {
                unsigned kh[4], kl[4];
                unsigned off = koff + (p * 16 * QKSTR) * 2 + kt * 32;
                ldsm4(kh, KHs + off);
                ldsm4(kl, KLs + off);
                // n-octet 0: b0=r0 (k0-7), b1=r2 (k8-15); n-octet 1: r1, r3
                mma16(sacc[2 * p],     ah, kh[0], kh[2]);
                mma16(sacc[2 * p],     ah, kl[0], kl[2]);
                mma16(sacc[2 * p],     al, kh[0], kh[2]);
                mma16(sacc[2 * p + 1], ah, kh[1], kh[3]);
                mma16(sacc[2 * p + 1], ah, kl[1], kl[3]);
                mma16(sacc[2 * p + 1], al, kh[1], kh[3]);
            }
        }

        asm volatile("cp.async.wait_group 0;\n");
        __syncthreads();
        CPK(npf);
        asm volatile("cp.async.commit_group;\n");

        // ---- scale + causal mask ----
#pragma unroll
        for (int nt = 0; nt < 8; nt++)
#pragma unroll
            for (int c = 0; c < 4; c++) {
                int col = n0 + nt * 8 + 2 * t + (c & 1);
                int row = m0 + warp * 16 + g + (c >> 1) * 8;
                float v = sacc[nt][c] * scale;
                if (col > row) v = -1e30f;
                sacc[nt][c] = v;
            }

        // ---- warp-local online softmax ----
        float alpha_[2];
#pragma unroll
        for (int hf = 0; hf < 2; hf++) {
            float pm = -1e30f;
#pragma unroll
            for (int nt = 0; nt < 8; nt++)
                pm = fmaxf(pm, fmaxf(sacc[nt][hf * 2], sacc[nt][hf * 2 + 1]));
            pm = fmaxf(pm, __shfl_xor_sync(0xffffffffu, pm, 1));
            pm = fmaxf(pm, __shfl_xor_sync(0xffffffffu, pm, 2));
            float mnew = fmaxf(mrow[hf], pm);
            alpha_[hf] = __expf(mrow[hf] - mnew);
            mrow[hf] = mnew;
            float ps = 0.f;
#pragma unroll
            for (int nt = 0; nt < 8; nt++)
#pragma unroll
                for (int k2 = 0; k2 < 2; k2++) {
                    int c = hf * 2 + k2;
                    float p = __expf(sacc[nt][c] - mnew);
                    sacc[nt][c] = p;
                    ps += p;
                }
            lrow[hf] = lrow[hf] * alpha_[hf] + ps;
        }
#pragma unroll
        for (int nt = 0; nt < 16; nt++)
#pragma unroll
            for (int c = 0; c < 4; c++)
                oacc[nt][c] *= alpha_[c >> 1];

        // ---- O += P V ----
#pragma unroll
        for (int kt = 0; kt < 4; kt++) {
            unsigned aph[4], apl[4];
            aph[0] = packsplit(sacc[2 * kt][0],     sacc[2 * kt][1],     apl[0]);
            aph[1] = packsplit(sacc[2 * kt][2],     sacc[2 * kt][3],     apl[1]);
            aph[2] = packsplit(sacc[2 * kt + 1][0], sacc[2 * kt + 1][1], apl[2]);
            aph[3] = packsplit(sacc[2 * kt + 1][2], sacc[2 * kt + 1][3], apl[3]);
#pragma unroll
            for (int p = 0; p < 8; p++) {
                unsigned vh[4], vl[4];
                unsigned off = voff + (kt * 16 * 136) * 2 + p * 32;
                ldsm4t(vh, VHs + off);
                ldsm4t(vl, VLs + off);
                // d-octet 0: b0=r0 (s0-7), b1=r1 (s8-15); d-octet 1: r2, r3
                mma16(oacc[2 * p],     aph, vh[0], vh[1]);
                mma16(oacc[2 * p],     aph, vl[0], vl[1]);
                mma16(oacc[2 * p],     apl, vh[0], vh[1]);
                mma16(oacc[2 * p + 1], aph, vh[2], vh[3]);
                mma16(oacc[2 * p + 1], aph, vl[2], vl[3]);
                mma16(oacc[2 * p + 1], apl, vh[2], vh[3]);
            }
        }

        __syncthreads();
        CPV(npf);
        asm volatile("cp.async.commit_group;\n");
        asm volatile("cp.async.wait_group 1;\n");
        __syncthreads();
    }
#undef CPK
#undef CPV

    // ---- epilogue: quad-reduce l, store AO as tf32 bits (A-permuted) ----
#pragma unroll
    for (int hf = 0; hf < 2; hf++) {
        float lq = lrow[hf];
        lq += __shfl_xor_sync(0xffffffffu, lq, 1);
        lq += __shfl_xor_sync(0xffffffffu, lq, 2);
        float inv = 1.f / lq;
        int row = m0 + warp * 16 + hf * 8 + g;
#pragma unroll
        for (int nt = 0; nt < 16; nt++) {
            int col = nt * 8 + 2 * t;
            int base = col & ~7;
            int o0 = pa8(col & 7);
            unsigned* dst = g_AO + (size_t)row * (NH * HD) + h * HD + base;
            dst[o0]     = f2tf(oacc[nt][hf * 2]     * inv);
            dst[o0 + 2] = f2tf(oacc[nt][hf * 2 + 1] * inv);
        }
    }
}

// ---------------- launch ----------------------------------------------------
extern "C" void kernel_launch(void* const* d_in, const int* in_sizes, int n_in,
                              void* d_out, int out_size)
{
    const float* X     = (const float*)d_in[0];
    const float* W_DKV = (const float*)d_in[2];
    const float* W_UK  = (const float*)d_in[3];
    const float* W_UV  = (const float*)d_in[4];
    const float* W_DQ  = (const float*)d_in[5];
    const float* W_UQ  = (const float*)d_in[6];
    const float* W_QR  = (const float*)d_in[7];
    const float* W_KR  = (const float*)d_in[8];
    const float* W_O   = (const float*)d_in[9];
    float* out = (float*)d_out;

    unsigned *Xt, *Wdkv, *Wuk, *Wuv, *Wdq, *Wuq, *Wqr, *Wkr, *Wo;
    unsigned *cKVt, *cQt, *AO;
    float *qR, *kR;
    unsigned short *QHp, *QLp, *KHp, *KLp, *VHp, *VLp;
    cudaGetSymbolAddress((void**)&Xt,   g_Xt);
    cudaGetSymbolAddress((void**)&Wdkv, g_Wdkv);
    cudaGetSymbolAddress((void**)&Wuk,  g_Wuk);
    cudaGetSymbolAddress((void**)&Wuv,  g_Wuv);
    cudaGetSymbolAddress((void**)&Wdq,  g_Wdq);
    cudaGetSymbolAddress((void**)&Wuq,  g_Wuq);
    cudaGetSymbolAddress((void**)&Wqr,  g_Wqr);
    cudaGetSymbolAddress((void**)&Wkr,  g_Wkr);
    cudaGetSymbolAddress((void**)&Wo,   g_Wo);
    cudaGetSymbolAddress((void**)&cKVt, g_cKVt);
    cudaGetSymbolAddress((void**)&cQt,  g_cQt);
    cudaGetSymbolAddress((void**)&AO,   g_AO);
    cudaGetSymbolAddress((void**)&qR,   g_qR);
    cudaGetSymbolAddress((void**)&kR,   g_kR);
    cudaGetSymbolAddress((void**)&QHp,  g_QH);
    cudaGetSymbolAddress((void**)&QLp,  g_QL);
    cudaGetSymbolAddress((void**)&KHp,  g_KH);
    cudaGetSymbolAddress((void**)&KLp,  g_KL);
    cudaGetSymbolAddress((void**)&VHp,  g_VH2);
    cudaGetSymbolAddress((void**)&VLp,  g_VL2);

    dim3 blk(256);

    // 0) preconvert all GEMM operands
    {
        CvtArgs ca = {};
        const float* srcs[9] = {X, W_DKV, W_UK, W_UV, W_DQ, W_UQ, W_QR, W_KR, W_O};
        unsigned* dsts[9] = {Xt, Wdkv, Wuk, Wuv, Wdq, Wuq, Wqr, Wkr, Wo};
        int sizes[9] = {S_LEN * HID_D, HID_D * CKV, CKV * NH * HD, CKV * NH * HD,
                        HID_D * CQ, CQ * NH * HD, CQ * NH * DR, HID_D * DR,
                        NH * HD * HID_D};
        int acc = 0;
        for (int i = 0; i < 9; i++) {
            ca.src[i] = srcs[i];
            ca.dst[i] = dsts[i];
            ca.tstart[i] = acc;
            ca.perm[i] = (i == 0) ? 1 : 0;
            acc += sizes[i] / 1024;
        }
        ca.tstart[9] = acc;
        cvt_kernel<<<acc, blk>>>(ca);
    }

    cudaFuncSetAttribute(mma_gemm_grouped,
                         cudaFuncAttributeMaxDynamicSharedMemorySize, GEMM_SMEM);

    // P1: Xt @ {Wdq->cQt, Wdkv->cKVt, Wkr->kR}
    {
        GroupArgs ga = {};
        ga.A[0] = Xt; ga.B[0] = Wdq;  ga.C[0] = cQt;  ga.K[0] = HID_D; ga.N[0] = CQ;  ga.mode[0] = 3;
        ga.A[1] = Xt; ga.B[1] = Wdkv; ga.C[1] = cKVt; ga.K[1] = HID_D; ga.N[1] = CKV; ga.mode[1] = 3;
        ga.A[2] = Xt; ga.B[2] = Wkr;  ga.C[2] = kR;   ga.K[2] = HID_D; ga.N[2] = DR;  ga.mode[2] = 0;
        ga.tstart[0] = 0; ga.tstart[1] = 12; ga.tstart[2] = 16; ga.tstart[3] = 17; ga.tstart[4] = 17;
        mma_gemm_grouped<<<dim3(16, 17), blk, GEMM_SMEM>>>(ga);
    }
    // P2: {Wuq->bf16 Q, Wqr->qR, Wuk->bf16 K, Wuv->bf16 V}
    {
        GroupArgs ga = {};
        ga.A[0] = cQt;  ga.B[0] = Wuq; ga.C[0] = QHp; ga.Clo[0] = QLp; ga.K[0] = CQ;  ga.N[0] = NH * HD; ga.mode[0] = 1;
        ga.A[1] = cQt;  ga.B[1] = Wqr; ga.C[1] = qR;                   ga.K[1] = CQ;  ga.N[1] = NH * DR; ga.mode[1] = 0;
        ga.A[2] = cKVt; ga.B[2] = Wuk; ga.C[2] = KHp; ga.Clo[2] = KLp; ga.K[2] = CKV; ga.N[2] = NH * HD; ga.mode[2] = 1;
        ga.A[3] = cKVt; ga.B[3] = Wuv; ga.C[3] = VHp; ga.Clo[3] = VLp; ga.K[3] = CKV; ga.N[3] = NH * HD; ga.mode[3] = 4;
        ga.tstart[0] = 0; ga.tstart[1] = 16; ga.tstart[2] = 24; ga.tstart[3] = 40; ga.tstart[4] = 56;
        mma_gemm_grouped<<<dim3(16, 56), blk, GEMM_SMEM>>>(ga);
    }

    rope_q_kernel<<<(S_LEN * NH * 32) / 256, 256>>>();
    rope_k_kernel<<<(S_LEN * 32) / 256, 256>>>();

    cudaFuncSetAttribute(attn_mma_kernel, cudaFuncAttributeMaxDynamicSharedMemorySize, ATTN_SMEM);
    attn_mma_kernel<<<256, 256, ATTN_SMEM>>>();

    // WO: AO @ Wo -> out
    {
        GroupArgs ga = {};
        ga.A[0] = AO; ga.B[0] = Wo; ga.C[0] = out; ga.K[0] = NH * HD; ga.N[0] = HID_D; ga.mode[0] = 0;
        ga.tstart[0] = 0; ga.tstart[1] = 16; ga.tstart[2] = 16; ga.tstart[3] = 16; ga.tstart[4] = 16;
        mma_gemm_grouped<<<dim3(16, 16), blk, GEMM_SMEM>>>(ga);
    }
}